// round 2
// baseline (speedup 1.0000x reference)
#include <cuda_runtime.h>
#include <math.h>

// Problem constants (fixed by reference)
#define B_SAMPLES 512
#define M_ROWS    24
#define D_DIM     4096
#define CHUNK     128
#define NSTAGE    (D_DIM / CHUNK)   // 32
#define THREADS   256
#define NTILE     21                // upper-triangular 4x4 tiles of 6x6 grid
#define NKG       12                // k-slice groups
#define NCOMP     (NTILE * NKG)     // 252 compute threads

__device__ float g_scratch[B_SAMPLES];

__constant__ int c_ti[NTILE] = {0,0,0,0,0,0,1,1,1,1,1,2,2,2,2,3,3,3,4,4,5};
__constant__ int c_tj[NTILE] = {0,1,2,3,4,5,1,2,3,4,5,2,3,4,5,3,4,5,4,5,5};

// Swizzled smem offset: conflict-free for float4 STS (per-row) and for the
// scalar LDS pattern in the gram loop (rows are multiples of 4; swizzle keyed
// on r>>2 so rows 4i..4i+3 share one XOR and distinct i land on distinct banks).
__device__ __forceinline__ int soff(int r, int k) {
    return r * CHUNK + (k ^ (((r >> 2) & 7) << 2));
}

__global__ __launch_bounds__(THREADS)
void gram_loss_kernel(const float* __restrict__ feat) {
    __shared__ float sbuf[2][M_ROWS * CHUNK];     // 24 KB double buffer
    __shared__ float spart[NKG][NTILE * 16];      // 15.75 KB partials
    __shared__ float sG[M_ROWS][M_ROWS];
    __shared__ float sinv[M_ROWS];

    const int tid = threadIdx.x;
    const int b   = blockIdx.x;
    const float* base = feat + (size_t)b * (M_ROWS * D_DIM);

    const int  tile   = tid % NTILE;
    const int  kg     = tid / NTILE;
    const bool active = (tid < NCOMP);
    int ra = 0, rb = 0;
    if (active) { ra = 4 * c_ti[tile]; rb = 4 * c_tj[tile]; }

    float acc[16];
#pragma unroll
    for (int e = 0; e < 16; e++) acc[e] = 0.f;

    // ---- prologue: stage 0 into buffer 0 ----
    float4 nxt[3];
#pragma unroll
    for (int u = 0; u < 3; u++) {
        int e = tid + u * THREADS;           // 768 float4 per stage, 3 per thread
        int r = e >> 5, kq = e & 31;
        nxt[u] = *reinterpret_cast<const float4*>(base + r * D_DIM + kq * 4);
    }
#pragma unroll
    for (int u = 0; u < 3; u++) {
        int e = tid + u * THREADS;
        int r = e >> 5, kq = e & 31;
        *reinterpret_cast<float4*>(&sbuf[0][soff(r, kq * 4)]) = nxt[u];
    }
    __syncthreads();

    // ---- main loop: LDG(s+1) overlaps compute(s) ----
    for (int s = 0; s < NSTAGE; ++s) {
        if (s + 1 < NSTAGE) {
#pragma unroll
            for (int u = 0; u < 3; u++) {
                int e = tid + u * THREADS;
                int r = e >> 5, kq = e & 31;
                nxt[u] = *reinterpret_cast<const float4*>(
                    base + r * D_DIM + (s + 1) * CHUNK + kq * 4);
            }
        }
        if (active) {
            const float* cur = sbuf[s & 1];
            for (int k = kg; k < CHUNK; k += NKG) {
                float av[4], bv[4];
#pragma unroll
                for (int c = 0; c < 4; c++) av[c] = cur[soff(ra + c, k)];
#pragma unroll
                for (int c = 0; c < 4; c++) bv[c] = cur[soff(rb + c, k)];
#pragma unroll
                for (int a = 0; a < 4; a++)
#pragma unroll
                    for (int c2 = 0; c2 < 4; c2++)
                        acc[a * 4 + c2] = fmaf(av[a], bv[c2], acc[a * 4 + c2]);
            }
        }
        if (s + 1 < NSTAGE) {
            __syncthreads();   // all reads of buf[(s+1)&1] (stage s-1) done
#pragma unroll
            for (int u = 0; u < 3; u++) {
                int e = tid + u * THREADS;
                int r = e >> 5, kq = e & 31;
                *reinterpret_cast<float4*>(&sbuf[(s + 1) & 1][soff(r, kq * 4)]) = nxt[u];
            }
            __syncthreads();   // stage s+1 visible
        }
    }

    // ---- cross-kg reduction into full symmetric G ----
    if (active) {
#pragma unroll
        for (int e = 0; e < 16; e++) spart[kg][tile * 16 + e] = acc[e];
    }
    __syncthreads();
    for (int idx = tid; idx < NTILE * 16; idx += THREADS) {
        float v = 0.f;
#pragma unroll
        for (int g = 0; g < NKG; g++) v += spart[g][idx];
        int t2 = idx >> 4, e = idx & 15;
        int r = 4 * c_ti[t2] + (e >> 2);
        int c = 4 * c_tj[t2] + (e & 3);
        sG[r][c] = v;
        sG[c][r] = v;
    }
    __syncthreads();

    // ---- epilogue: norms ----
    if (tid < M_ROWS) {
        float nr = sqrtf(sG[tid][tid]);
        sinv[tid] = 1.0f / fmaxf(nr, 1e-12f);
    }
    __syncthreads();

    // ---- per-anchor masked log-softmax (matches reference: no max-sub) ----
    float mlpp = 0.f;
    if (tid < M_ROWS) {
        const int m = tid;
        const float im = sinv[m];
        const int cm = m % 12;
        float denom = 0.f, possum = 0.f, cnt = 0.f;
#pragma unroll
        for (int n = 0; n < M_ROWS; ++n) {
            if (n == m) continue;
            float logit = sG[m][n] * im * sinv[n] * 10.0f;   // /T, T=0.1
            denom += expf(logit);
            int cn = n % 12;
            int dc = cm - cn; if (dc < 0) dc = -dc;
            if (dc <= 1) { possum += logit; cnt += 1.f; }
        }
        mlpp = (possum - cnt * logf(denom)) / (cnt + 1e-6f);
    }
    if (tid < 32) {
        float v = mlpp;   // lanes 24..31 contribute 0
#pragma unroll
        for (int o = 16; o > 0; o >>= 1)
            v += __shfl_down_sync(0xffffffffu, v, o);
        if (tid == 0)
            g_scratch[b] = v * (-0.1f / 24.0f);   // -(T/base) * mean over M
    }
}

// Deterministic final reduction: sum 512 per-sample losses, divide by B.
__global__ void reduce_kernel(float* __restrict__ out) {
    __shared__ float s[256];
    int t = threadIdx.x;
    s[t] = g_scratch[t] + g_scratch[t + 256];
    __syncthreads();
#pragma unroll
    for (int w = 128; w > 0; w >>= 1) {
        if (t < w) s[t] += s[t + w];
        __syncthreads();
    }
    if (t == 0) out[0] = s[0] * (1.0f / (float)B_SAMPLES);
}

extern "C" void kernel_launch(void* const* d_in, const int* in_sizes, int n_in,
                              void* d_out, int out_size) {
    // metadata order: outputs (f32), targets (i32), features (f32) — only
    // features participate in the loss.
    const float* feat = (const float*)d_in[2];
    gram_loss_kernel<<<B_SAMPLES, THREADS>>>(feat);
    reduce_kernel<<<1, 256>>>((float*)d_out);
}

// round 3
// speedup vs baseline: 1.2347x; 1.2347x over previous
#include <cuda_runtime.h>
#include <math.h>

// Problem constants (fixed by reference)
#define B_SAMPLES 512
#define M_ROWS    24
#define D_DIM     4096
#define CHUNK     128
#define NPAIR     (CHUNK / 2)       // 64 k-pairs per stage
#define NSTAGE    (D_DIM / CHUNK)   // 32
#define THREADS   256
#define NTILE     21                // upper-triangular 4x4 tiles of 6x6 grid
#define NKG       12                // k-pair groups
#define NCOMP     (NTILE * NKG)     // 252 compute threads

__device__ float g_scratch[B_SAMPLES];

__constant__ int c_ti[NTILE] = {0,0,0,0,0,0,1,1,1,1,1,2,2,2,2,3,3,3,4,4,5};
__constant__ int c_tj[NTILE] = {0,1,2,3,4,5,1,2,3,4,5,2,3,4,5,3,4,5,4,5,5};

// Swizzled smem offset (in floats). Conflict-free for float4 STS per row and
// keeps 8-byte alignment for the 64-bit LDS in the gram loop (k even, xor is a
// multiple of 4).
__device__ __forceinline__ int soff(int r, int k) {
    return r * CHUNK + (k ^ (((r >> 2) & 7) << 2));
}

// 64-bit shared load straight into a packed f32x2 register pair.
__device__ __forceinline__ unsigned long long lds64(unsigned int saddr) {
    unsigned long long v;
    asm volatile("ld.shared.b64 %0, [%1];" : "=l"(v) : "r"(saddr));
    return v;
}
// Packed dual-FMA: d.lo += a.lo*b.lo ; d.hi += a.hi*b.hi  (sm_100+)
__device__ __forceinline__ void ffma2(unsigned long long& d,
                                      unsigned long long a,
                                      unsigned long long b) {
    asm volatile("fma.rn.f32x2 %0, %1, %2, %0;" : "+l"(d) : "l"(a), "l"(b));
}
__device__ __forceinline__ float2 unpack2(unsigned long long v) {
    float2 f;
    asm volatile("mov.b64 {%0, %1}, %2;" : "=f"(f.x), "=f"(f.y) : "l"(v));
    return f;
}

__global__ __launch_bounds__(THREADS)
void gram_loss_kernel(const float* __restrict__ feat) {
    // Pool: double buffer [2][24*128] floats = 24 KB. The spart partial array
    // (12*336 floats) is overlaid on the pool after the main loop (guarded by
    // a barrier) to keep smem at ~26.5 KB for multi-CTA residency.
    __shared__ float pool[2 * M_ROWS * CHUNK];
    __shared__ float sG[M_ROWS][M_ROWS];
    __shared__ float sinv[M_ROWS];

    const int tid = threadIdx.x;
    const int b   = blockIdx.x;
    const float* base = feat + (size_t)b * (M_ROWS * D_DIM);

    const int  tile   = tid % NTILE;
    const int  kg     = tid / NTILE;
    const bool active = (tid < NCOMP);
    int ra = 0, rb = 0;
    if (active) { ra = 4 * c_ti[tile]; rb = 4 * c_tj[tile]; }

    // shared-state-space byte addresses of the two buffers
    const unsigned int pbase = (unsigned int)__cvta_generic_to_shared(pool);

    unsigned long long acc[16];
#pragma unroll
    for (int e = 0; e < 16; e++) acc[e] = 0ull;

    // ---- prologue: stage 0 into buffer 0 ----
    float4 nxt[3];
#pragma unroll
    for (int u = 0; u < 3; u++) {
        int e = tid + u * THREADS;           // 768 float4 per stage
        int r = e >> 5, kq = e & 31;
        nxt[u] = *reinterpret_cast<const float4*>(base + r * D_DIM + kq * 4);
    }
#pragma unroll
    for (int u = 0; u < 3; u++) {
        int e = tid + u * THREADS;
        int r = e >> 5, kq = e & 31;
        *reinterpret_cast<float4*>(&pool[soff(r, kq * 4)]) = nxt[u];
    }
    __syncthreads();

    // ---- main loop: LDG(s+1) overlaps compute(s) ----
    for (int s = 0; s < NSTAGE; ++s) {
        if (s + 1 < NSTAGE) {
#pragma unroll
            for (int u = 0; u < 3; u++) {
                int e = tid + u * THREADS;
                int r = e >> 5, kq = e & 31;
                nxt[u] = *reinterpret_cast<const float4*>(
                    base + r * D_DIM + (s + 1) * CHUNK + kq * 4);
            }
        }
        if (active) {
            const unsigned int cur = pbase + (unsigned int)((s & 1) * M_ROWS * CHUNK * 4);
            // k-pairs: thread kg handles p = kg, kg+12, ... (< 64)
            for (int p = kg; p < NPAIR; p += NKG) {
                const int k = 2 * p;
                unsigned long long av[4], bv[4];
#pragma unroll
                for (int c = 0; c < 4; c++) av[c] = lds64(cur + 4u * soff(ra + c, k));
#pragma unroll
                for (int c = 0; c < 4; c++) bv[c] = lds64(cur + 4u * soff(rb + c, k));
#pragma unroll
                for (int a = 0; a < 4; a++)
#pragma unroll
                    for (int c2 = 0; c2 < 4; c2++)
                        ffma2(acc[a * 4 + c2], av[a], bv[c2]);
            }
        }
        if (s + 1 < NSTAGE) {
            __syncthreads();   // all reads of buf[(s+1)&1] (stage s-1) done
#pragma unroll
            for (int u = 0; u < 3; u++) {
                int e = tid + u * THREADS;
                int r = e >> 5, kq = e & 31;
                *reinterpret_cast<float4*>(
                    &pool[((s + 1) & 1) * M_ROWS * CHUNK + soff(r, kq * 4)]) = nxt[u];
            }
            __syncthreads();   // stage s+1 visible
        }
    }

    // ---- cross-kg reduction into full symmetric G ----
    __syncthreads();                       // main-loop reads of pool complete
    float* spart = pool;                   // overlay: [NKG][NTILE*16]
    if (active) {
#pragma unroll
        for (int e = 0; e < 16; e++) {
            float2 f = unpack2(acc[e]);
            spart[kg * (NTILE * 16) + tile * 16 + e] = f.x + f.y;
        }
    }
    __syncthreads();
    for (int idx = tid; idx < NTILE * 16; idx += THREADS) {
        float v = 0.f;
#pragma unroll
        for (int g = 0; g < NKG; g++) v += spart[g * (NTILE * 16) + idx];
        int t2 = idx >> 4, e = idx & 15;
        int r = 4 * c_ti[t2] + (e >> 2);
        int c = 4 * c_tj[t2] + (e & 3);
        sG[r][c] = v;
        sG[c][r] = v;
    }
    __syncthreads();

    // ---- epilogue: norms ----
    if (tid < M_ROWS) {
        float nr = sqrtf(sG[tid][tid]);
        sinv[tid] = 1.0f / fmaxf(nr, 1e-12f);
    }
    __syncthreads();

    // ---- per-anchor masked log-softmax (matches reference: no max-sub) ----
    float mlpp = 0.f;
    if (tid < M_ROWS) {
        const int m = tid;
        const float im = sinv[m];
        const int cm = m % 12;
        float denom = 0.f, possum = 0.f, cnt = 0.f;
#pragma unroll
        for (int n = 0; n < M_ROWS; ++n) {
            if (n == m) continue;
            float logit = sG[m][n] * im * sinv[n] * 10.0f;   // /T, T=0.1
            denom += expf(logit);
            int cn = n % 12;
            int dc = cm - cn; if (dc < 0) dc = -dc;
            if (dc <= 1) { possum += logit; cnt += 1.f; }
        }
        mlpp = (possum - cnt * logf(denom)) / (cnt + 1e-6f);
    }
    if (tid < 32) {
        float v = mlpp;   // lanes 24..31 contribute 0
#pragma unroll
        for (int o = 16; o > 0; o >>= 1)
            v += __shfl_down_sync(0xffffffffu, v, o);
        if (tid == 0)
            g_scratch[b] = v * (-0.1f / 24.0f);   // -(T/base) * mean over M
    }
}

// Deterministic final reduction: sum 512 per-sample losses, divide by B.
__global__ void reduce_kernel(float* __restrict__ out) {
    __shared__ float s[256];
    int t = threadIdx.x;
    s[t] = g_scratch[t] + g_scratch[t + 256];
    __syncthreads();
#pragma unroll
    for (int w = 128; w > 0; w >>= 1) {
        if (t < w) s[t] += s[t + w];
        __syncthreads();
    }
    if (t == 0) out[0] = s[0] * (1.0f / (float)B_SAMPLES);
}

extern "C" void kernel_launch(void* const* d_in, const int* in_sizes, int n_in,
                              void* d_out, int out_size) {
    const float* feat = (const float*)d_in[2];
    gram_loss_kernel<<<B_SAMPLES, THREADS>>>(feat);
    reduce_kernel<<<1, 256>>>((float*)d_out);
}